// round 2
// baseline (speedup 1.0000x reference)
#include <cuda_runtime.h>
#include <cuda_bf16.h>

#define HH 256
#define WW 256
#define NIMG (64*21)
#define TILE_X 128
#define TILE_Y 64
#define SROWS (TILE_Y + 8)    // 72
#define SSTRIDE (TILE_X + 8)  // 136 floats per smem row (544B, 16B-aligned)

__global__ __launch_bounds__(256, 2)
void heatmap_sepconv_kernel(const int* __restrict__ coords,
                            const float* __restrict__ noise,
                            const float* __restrict__ k2d,
                            float* __restrict__ out)
{
    __shared__ float sk[81];
    __shared__ __align__(16) float sin_[SROWS * SSTRIDE];  // 39168 B

    const int tid = threadIdx.x;
    const int img = blockIdx.z;
    const int x0 = blockIdx.x * TILE_X;
    const int y0 = blockIdx.y * TILE_Y;

    if (tid < 81) sk[tid] = k2d[tid];

    const int cx = coords[2 * img];
    const int cy = coords[2 * img + 1];
    const float gval = 1.0f / __ldg(&k2d[40]);  // peak value = 1/max(kernel2d)

    const float* __restrict__ np = noise + (size_t)img * (HH * WW);

    // Load haloed tile: scaled noise, zero padding, peak injection.
    #pragma unroll 4
    for (int s = tid; s < SROWS * SSTRIDE; s += 256) {
        int ir = s / SSTRIDE;
        int ic = s - ir * SSTRIDE;
        int gy = y0 - 4 + ir;
        int gx = x0 - 4 + ic;
        float v = 0.0f;
        if (gy >= 0 && gy < HH && gx >= 0 && gx < WW) {
            v = 0.01f * np[gy * WW + gx];
            if (gy == cy && gx == cx) v = gval;
        }
        sin_[s] = v;
    }
    __syncthreads();

    // 1D gaussian from row sums of the 2D kernel (broadcast LDS, cheap).
    float g[9];
    #pragma unroll
    for (int i = 0; i < 9; i++) {
        float s = 0.0f;
        #pragma unroll
        for (int j = 0; j < 9; j++) s += sk[i * 9 + j];
        g[i] = s;
    }

    // Thread owns 4 consecutive columns x 8 output rows.
    const int tx = tid & 31;        // 32 column groups
    const int ty = tid >> 5;        // 8 row groups
    const int cbase = tx * 4;       // 0..124 (16B-aligned in smem row)
    const int r0 = ty * 8;          // 0..56

    // Horizontal pass: 16 tmp rows (8 outputs + 8 halo) kept in registers.
    float tmp[16][4];
    #pragma unroll
    for (int rr = 0; rr < 16; rr++) {
        const float* row = &sin_[(r0 + rr) * SSTRIDE + cbase];
        float4 a = *(const float4*)(row);
        float4 b = *(const float4*)(row + 4);
        float4 c = *(const float4*)(row + 8);
        float v[12] = {a.x, a.y, a.z, a.w, b.x, b.y, b.z, b.w, c.x, c.y, c.z, c.w};
        #pragma unroll
        for (int cc = 0; cc < 4; cc++) {
            float s = 0.0f;
            #pragma unroll
            for (int j = 0; j < 9; j++) s = fmaf(g[j], v[cc + j], s);
            tmp[rr][cc] = s;
        }
    }

    // Vertical pass: register-only sliding window, ReLU, float4 stores.
    const size_t obase = (size_t)img * (HH * WW);
    #pragma unroll
    for (int rr = 0; rr < 8; rr++) {
        float acc0 = 0.f, acc1 = 0.f, acc2 = 0.f, acc3 = 0.f;
        #pragma unroll
        for (int i = 0; i < 9; i++) {
            acc0 = fmaf(g[i], tmp[rr + i][0], acc0);
            acc1 = fmaf(g[i], tmp[rr + i][1], acc1);
            acc2 = fmaf(g[i], tmp[rr + i][2], acc2);
            acc3 = fmaf(g[i], tmp[rr + i][3], acc3);
        }
        int gy = y0 + r0 + rr;
        float4 ov = make_float4(fmaxf(acc0, 0.f), fmaxf(acc1, 0.f),
                                fmaxf(acc2, 0.f), fmaxf(acc3, 0.f));
        *(float4*)(out + obase + (size_t)gy * WW + x0 + cbase) = ov;
    }
}

extern "C" void kernel_launch(void* const* d_in, const int* in_sizes, int n_in,
                              void* d_out, int out_size)
{
    // Identify inputs by element count (robust to ordering):
    //   coords: 64*21*2 = 2688 int32; kernel2d: 81 fp32; noise: 64*21*256*256 fp32.
    const int* coords = nullptr;
    const float* noise = nullptr;
    const float* k2d = nullptr;
    for (int i = 0; i < n_in; i++) {
        if (in_sizes[i] == 81)            k2d    = (const float*)d_in[i];
        else if (in_sizes[i] == 64*21*2)  coords = (const int*)d_in[i];
        else                              noise  = (const float*)d_in[i];
    }

    dim3 grid(WW / TILE_X, HH / TILE_Y, NIMG);
    heatmap_sepconv_kernel<<<grid, 256>>>(coords, noise, k2d, (float*)d_out);
}

// round 3
// speedup vs baseline: 1.0464x; 1.0464x over previous
#include <cuda_runtime.h>
#include <cuda_bf16.h>

#define HH 256
#define WW 256
#define NIMG (64*21)
#define TILE_X 128
#define TILE_Y 64
#define SROWS (TILE_Y + 8)    // 72
#define SSTRIDE (TILE_X + 8)  // 136 floats per smem row (544B, 16B-aligned)

__global__ __launch_bounds__(256, 2)
void heatmap_sepconv_kernel(const int* __restrict__ coords,
                            const float* __restrict__ noise,
                            const float* __restrict__ k2d,
                            float* __restrict__ out)
{
    __shared__ float sk[81];
    __shared__ __align__(16) float sin_[SROWS * SSTRIDE];  // 39168 B

    const int tid = threadIdx.x;
    const int img = blockIdx.z;
    const int x0 = blockIdx.x * TILE_X;
    const int y0 = blockIdx.y * TILE_Y;

    if (tid < 81) sk[tid] = k2d[tid];

    const int cx = coords[2 * img];
    const int cy = coords[2 * img + 1];
    const float gval = 1.0f / __ldg(&k2d[40]);  // peak value = 1/max(kernel2d)

    const float* __restrict__ np = noise + (size_t)img * (HH * WW);

    // Load haloed tile: scaled noise, zero padding, peak injection.
    #pragma unroll 4
    for (int s = tid; s < SROWS * SSTRIDE; s += 256) {
        int ir = s / SSTRIDE;
        int ic = s - ir * SSTRIDE;
        int gy = y0 - 4 + ir;
        int gx = x0 - 4 + ic;
        float v = 0.0f;
        if (gy >= 0 && gy < HH && gx >= 0 && gx < WW) {
            v = 0.01f * np[gy * WW + gx];
            if (gy == cy && gx == cx) v = gval;
        }
        sin_[s] = v;
    }
    __syncthreads();

    // 1D gaussian from row sums of the 2D kernel (broadcast LDS, cheap).
    float g[9];
    #pragma unroll
    for (int i = 0; i < 9; i++) {
        float s = 0.0f;
        #pragma unroll
        for (int j = 0; j < 9; j++) s += sk[i * 9 + j];
        g[i] = s;
    }

    // Thread owns 4 consecutive columns x 8 output rows.
    const int tx = tid & 31;        // 32 column groups
    const int ty = tid >> 5;        // 8 row groups
    const int cbase = tx * 4;       // 0..124 (16B-aligned in smem row)
    const int r0 = ty * 8;          // 0..56

    // Horizontal pass: 16 tmp rows (8 outputs + 8 halo) kept in registers.
    float tmp[16][4];
    #pragma unroll
    for (int rr = 0; rr < 16; rr++) {
        const float* row = &sin_[(r0 + rr) * SSTRIDE + cbase];
        float4 a = *(const float4*)(row);
        float4 b = *(const float4*)(row + 4);
        float4 c = *(const float4*)(row + 8);
        float v[12] = {a.x, a.y, a.z, a.w, b.x, b.y, b.z, b.w, c.x, c.y, c.z, c.w};
        #pragma unroll
        for (int cc = 0; cc < 4; cc++) {
            float s = 0.0f;
            #pragma unroll
            for (int j = 0; j < 9; j++) s = fmaf(g[j], v[cc + j], s);
            tmp[rr][cc] = s;
        }
    }

    // Vertical pass: register-only sliding window, ReLU, float4 stores.
    const size_t obase = (size_t)img * (HH * WW);
    #pragma unroll
    for (int rr = 0; rr < 8; rr++) {
        float acc0 = 0.f, acc1 = 0.f, acc2 = 0.f, acc3 = 0.f;
        #pragma unroll
        for (int i = 0; i < 9; i++) {
            acc0 = fmaf(g[i], tmp[rr + i][0], acc0);
            acc1 = fmaf(g[i], tmp[rr + i][1], acc1);
            acc2 = fmaf(g[i], tmp[rr + i][2], acc2);
            acc3 = fmaf(g[i], tmp[rr + i][3], acc3);
        }
        int gy = y0 + r0 + rr;
        float4 ov = make_float4(fmaxf(acc0, 0.f), fmaxf(acc1, 0.f),
                                fmaxf(acc2, 0.f), fmaxf(acc3, 0.f));
        *(float4*)(out + obase + (size_t)gy * WW + x0 + cbase) = ov;
    }
}

extern "C" void kernel_launch(void* const* d_in, const int* in_sizes, int n_in,
                              void* d_out, int out_size)
{
    // Identify inputs by element count (robust to ordering):
    //   coords: 64*21*2 = 2688 int32; kernel2d: 81 fp32; noise: 64*21*256*256 fp32.
    const int* coords = nullptr;
    const float* noise = nullptr;
    const float* k2d = nullptr;
    for (int i = 0; i < n_in; i++) {
        if (in_sizes[i] == 81)            k2d    = (const float*)d_in[i];
        else if (in_sizes[i] == 64*21*2)  coords = (const int*)d_in[i];
        else                              noise  = (const float*)d_in[i];
    }

    dim3 grid(WW / TILE_X, HH / TILE_Y, NIMG);
    heatmap_sepconv_kernel<<<grid, 256>>>(coords, noise, k2d, (float*)d_out);
}